// round 2
// baseline (speedup 1.0000x reference)
#include <cuda_runtime.h>
#include <cuda_bf16.h>

// MGIoU2D+ loss: per-box (quad) marginalized GIoU over 8 candidate axes
// (edge normals of CCW-angle-sorted pred + target) plus convexity penalty.
// One thread per box. atan2-argsort replaced by exact angular comparator.

__device__ __forceinline__ bool ang_less(float ux, float uy, float vx, float vy) {
    // true iff atan2(uy,ux) < atan2(vy,vx)  (exact except measure-zero ties)
    bool lu = uy < 0.0f;   // lower half-plane: angles in (-pi, 0)
    bool lv = vy < 0.0f;
    if (lu != lv) return lu;                 // lower half sorts first
    return (ux * vy - uy * vx) > 0.0f;       // same half: CCW cross test
}

// Sort 4 relative vectors by angle (ascending, matching argsort(atan2)),
// then emit edge normals (ey, -ex) of the sorted polygon.
__device__ __forceinline__ void candidate_axes(const float x[4], const float y[4],
                                               float* __restrict__ ax,
                                               float* __restrict__ ay) {
    float cx = (x[0] + x[1] + x[2] + x[3]) * 0.25f;
    float cy = (y[0] + y[1] + y[2] + y[3]) * 0.25f;
    float ux[4], uy[4];
#pragma unroll
    for (int i = 0; i < 4; i++) { ux[i] = x[i] - cx; uy[i] = y[i] - cy; }

#define CMPSWAP(i, j)                                                        \
    {                                                                        \
        bool sw = ang_less(ux[j], uy[j], ux[i], uy[i]);                      \
        float sx = sw ? ux[j] : ux[i];                                       \
        float sy = sw ? uy[j] : uy[i];                                       \
        float bx = sw ? ux[i] : ux[j];                                       \
        float by = sw ? uy[i] : uy[j];                                       \
        ux[i] = sx; uy[i] = sy; ux[j] = bx; uy[j] = by;                      \
    }
    // 5-comparator sorting network for 4 elements
    CMPSWAP(0, 1) CMPSWAP(2, 3) CMPSWAP(0, 2) CMPSWAP(1, 3) CMPSWAP(1, 2)
#undef CMPSWAP

#pragma unroll
    for (int i = 0; i < 4; i++) {
        int j = (i + 1) & 3;
        float ex = ux[j] - ux[i];
        float ey = uy[j] - uy[i];
        ax[i] = ey;          // normal = (edge.y, -edge.x)
        ay[i] = -ex;
    }
}

__global__ __launch_bounds__(256)
void mgiou2dplus_kernel(const float4* __restrict__ pred4,
                        const float4* __restrict__ targ4,
                        float* __restrict__ out, int B) {
    int b = blockIdx.x * blockDim.x + threadIdx.x;
    if (b >= B) return;

    float4 p01 = pred4[2 * b];
    float4 p23 = pred4[2 * b + 1];
    float4 t01 = targ4[2 * b];
    float4 t23 = targ4[2 * b + 1];

    float px[4] = {p01.x, p01.z, p23.x, p23.z};
    float py[4] = {p01.y, p01.w, p23.y, p23.w};
    float tx[4] = {t01.x, t01.z, t23.x, t23.z};
    float ty[4] = {t01.y, t01.w, t23.y, t23.w};

    float ax[8], ay[8];
    candidate_axes(px, py, ax, ay);         // axes 0..3 from pred
    candidate_axes(tx, ty, ax + 4, ay + 4); // axes 4..7 from target

    float gsum = 0.0f;
#pragma unroll
    for (int a = 0; a < 8; a++) {
        float nx = ax[a], ny = ay[a];

        float d0 = fmaf(px[0], nx, py[0] * ny);
        float d1 = fmaf(px[1], nx, py[1] * ny);
        float d2 = fmaf(px[2], nx, py[2] * ny);
        float d3 = fmaf(px[3], nx, py[3] * ny);
        float mn1 = fminf(fminf(d0, d1), fminf(d2, d3));
        float mx1 = fmaxf(fmaxf(d0, d1), fmaxf(d2, d3));

        float e0 = fmaf(tx[0], nx, ty[0] * ny);
        float e1 = fmaf(tx[1], nx, ty[1] * ny);
        float e2 = fmaf(tx[2], nx, ty[2] * ny);
        float e3 = fmaf(tx[3], nx, ty[3] * ny);
        float mn2 = fminf(fminf(e0, e1), fminf(e2, e3));
        float mx2 = fmaxf(fmaxf(e0, e1), fmaxf(e2, e3));

        float inter = fmaxf(fminf(mx1, mx2) - fmaxf(mn1, mn2), 0.0f);
        float uni   = (mx1 - mn1) + (mx2 - mn2) - inter;
        float hull  = fmaxf(mx1, mx2) - fminf(mn1, mn2);
        gsum += __fdividef(inter, uni) - __fdividef(hull - uni, hull);
    }
    float mgiou = gsum * 0.125f;

    // convexity penalty on pred in ORIGINAL vertex order
    float cr[4];
#pragma unroll
    for (int i = 0; i < 4; i++) {
        int ip = (i + 3) & 3;
        int in = (i + 1) & 3;
        float e1x = px[ip] - px[i], e1y = py[ip] - py[i];
        float e2x = px[in] - px[i], e2y = py[in] - py[i];
        cr[i] = e1x * e2y - e1y * e2x;
    }
    float c0 = cr[0];
    // sign(where(|c0|<=0, 1, c0)): zero (either sign) -> +1
    float sref = (c0 > 0.0f) ? 1.0f : ((c0 < 0.0f) ? -1.0f : 1.0f);
    float pen = fmaxf(-sref * cr[0], 0.0f) + fmaxf(-sref * cr[1], 0.0f) +
                fmaxf(-sref * cr[2], 0.0f) + fmaxf(-sref * cr[3], 0.0f);
    pen *= 0.25f;

    out[b] = (1.0f - mgiou) * 0.5f + 0.1f * pen;
}

extern "C" void kernel_launch(void* const* d_in, const int* in_sizes, int n_in,
                              void* d_out, int out_size) {
    const float4* pred = (const float4*)d_in[0];
    const float4* targ = (const float4*)d_in[1];
    float* out = (float*)d_out;
    int B = in_sizes[0] / 8;  // [B,4,2] f32
    int threads = 256;
    int blocks = (B + threads - 1) / threads;
    mgiou2dplus_kernel<<<blocks, threads>>>(pred, targ, out, B);
}

// round 3
// speedup vs baseline: 1.1001x; 1.1001x over previous
#include <cuda_runtime.h>
#include <cuda_bf16.h>

// MGIoU2D+ loss, 2 boxes per thread for ILP.
// - atan2-argsort replaced by exact half-plane + cross comparator (5-comparator network)
// - own-axis projections use the shared-endpoint identity (3 dots instead of 4)
// - single fast divide per axis

__device__ __forceinline__ bool ang_less(float ux, float uy, float vx, float vy) {
    bool lu = uy < 0.0f;
    bool lv = vy < 0.0f;
    if (lu != lv) return lu;
    return (ux * vy - uy * vx) > 0.0f;
}

__device__ __forceinline__ void sort_angular(float u[4], float v[4]) {
#define CMPSWAP(i, j)                                                        \
    {                                                                        \
        bool sw = ang_less(u[j], v[j], u[i], v[i]);                          \
        float sx = sw ? u[j] : u[i];                                         \
        float sy = sw ? v[j] : v[i];                                         \
        float bx = sw ? u[i] : u[j];                                         \
        float by = sw ? v[i] : v[j];                                         \
        u[i] = sx; v[i] = sy; u[j] = bx; v[j] = by;                          \
    }
    CMPSWAP(0, 1) CMPSWAP(2, 3) CMPSWAP(0, 2) CMPSWAP(1, 3) CMPSWAP(1, 2)
#undef CMPSWAP
}

// GIoU1d terms for 4 axes owned by sorted poly S, against other poly O (orig order).
__device__ __forceinline__ float giou_axes(const float sx[4], const float sy[4],
                                           const float ox[4], const float oy[4]) {
    float g = 0.0f;
#pragma unroll
    for (int k = 0; k < 4; k++) {
        int k1 = (k + 1) & 3, k2 = (k + 2) & 3, k3 = (k + 3) & 3;
        float nx = sy[k1] - sy[k];
        float ny = sx[k] - sx[k1];   // normal = (e.y, -e.x)

        // own poly: endpoints of edge k project equally -> 3 distinct dots
        float a = fmaf(sx[k], nx, sy[k] * ny);
        float b = fmaf(sx[k2], nx, sy[k2] * ny);
        float c = fmaf(sx[k3], nx, sy[k3] * ny);
        float mn1 = fminf(a, fminf(b, c));
        float mx1 = fmaxf(a, fmaxf(b, c));

        float e0 = fmaf(ox[0], nx, oy[0] * ny);
        float e1 = fmaf(ox[1], nx, oy[1] * ny);
        float e2 = fmaf(ox[2], nx, oy[2] * ny);
        float e3 = fmaf(ox[3], nx, oy[3] * ny);
        float mn2 = fminf(fminf(e0, e1), fminf(e2, e3));
        float mx2 = fmaxf(fmaxf(e0, e1), fmaxf(e2, e3));

        float inter = fmaxf(fminf(mx1, mx2) - fmaxf(mn1, mn2), 0.0f);
        float uni   = (mx1 - mn1) + (mx2 - mn2) - inter;
        float hull  = fmaxf(mx1, mx2) - fminf(mn1, mn2);
        // inter/uni - (hull-uni)/hull == (inter*hull + uni*(uni-hull)) / (uni*hull)
        float num = fmaf(inter, hull, uni * (uni - hull));
        g += __fdividef(num, uni * hull);
    }
    return g;
}

__device__ __forceinline__ float box_loss(const float px[4], const float py[4],
                                          const float tx[4], const float ty[4]) {
    // sorted (centered) pred -> restore raw sorted
    float cpx = (px[0] + px[1] + px[2] + px[3]) * 0.25f;
    float cpy = (py[0] + py[1] + py[2] + py[3]) * 0.25f;
    float spx[4], spy[4];
#pragma unroll
    for (int i = 0; i < 4; i++) { spx[i] = px[i] - cpx; spy[i] = py[i] - cpy; }
    sort_angular(spx, spy);
#pragma unroll
    for (int i = 0; i < 4; i++) { spx[i] += cpx; spy[i] += cpy; }

    float ctx = (tx[0] + tx[1] + tx[2] + tx[3]) * 0.25f;
    float cty = (ty[0] + ty[1] + ty[2] + ty[3]) * 0.25f;
    float stx[4], sty[4];
#pragma unroll
    for (int i = 0; i < 4; i++) { stx[i] = tx[i] - ctx; sty[i] = ty[i] - cty; }
    sort_angular(stx, sty);
#pragma unroll
    for (int i = 0; i < 4; i++) { stx[i] += ctx; sty[i] += cty; }

    float gsum = giou_axes(spx, spy, tx, ty)   // 4 pred axes
               + giou_axes(stx, sty, px, py);  // 4 target axes
    float mgiou = gsum * 0.125f;

    // convexity penalty on pred in ORIGINAL vertex order
    float cr[4];
#pragma unroll
    for (int i = 0; i < 4; i++) {
        int ip = (i + 3) & 3, in = (i + 1) & 3;
        float e1x = px[ip] - px[i], e1y = py[ip] - py[i];
        float e2x = px[in] - px[i], e2y = py[in] - py[i];
        cr[i] = e1x * e2y - e1y * e2x;
    }
    float c0 = cr[0];
    float sref = (c0 < 0.0f) ? -1.0f : 1.0f;   // zero -> +1
    float pen = fmaxf(-sref * cr[0], 0.0f) + fmaxf(-sref * cr[1], 0.0f) +
                fmaxf(-sref * cr[2], 0.0f) + fmaxf(-sref * cr[3], 0.0f);

    return fmaf(pen, 0.025f, (1.0f - mgiou) * 0.5f);  // 0.1 * pen/4
}

__global__ __launch_bounds__(128)
void mgiou2dplus_kernel(const float4* __restrict__ pred4,
                        const float4* __restrict__ targ4,
                        float* __restrict__ out, int B) {
    int t = blockIdx.x * blockDim.x + threadIdx.x;
    int b0 = 2 * t;
    if (b0 >= B) return;
    int b1 = (b0 + 1 < B) ? (b0 + 1) : b0;   // clamp (B even in practice)

    // load both boxes up front (independent scoreboards)
    float4 pA0 = pred4[2 * b0], pA1 = pred4[2 * b0 + 1];
    float4 tA0 = targ4[2 * b0], tA1 = targ4[2 * b0 + 1];
    float4 pB0 = pred4[2 * b1], pB1 = pred4[2 * b1 + 1];
    float4 tB0 = targ4[2 * b1], tB1 = targ4[2 * b1 + 1];

    float pxA[4] = {pA0.x, pA0.z, pA1.x, pA1.z};
    float pyA[4] = {pA0.y, pA0.w, pA1.y, pA1.w};
    float txA[4] = {tA0.x, tA0.z, tA1.x, tA1.z};
    float tyA[4] = {tA0.y, tA0.w, tA1.y, tA1.w};

    float pxB[4] = {pB0.x, pB0.z, pB1.x, pB1.z};
    float pyB[4] = {pB0.y, pB0.w, pB1.y, pB1.w};
    float txB[4] = {tB0.x, tB0.z, tB1.x, tB1.z};
    float tyB[4] = {tB0.y, tB0.w, tB1.y, tB1.w};

    float lossA = box_loss(pxA, pyA, txA, tyA);
    float lossB = box_loss(pxB, pyB, txB, tyB);

    out[b0] = lossA;
    if (b0 + 1 < B) out[b0 + 1] = lossB;
}

extern "C" void kernel_launch(void* const* d_in, const int* in_sizes, int n_in,
                              void* d_out, int out_size) {
    const float4* pred = (const float4*)d_in[0];
    const float4* targ = (const float4*)d_in[1];
    float* out = (float*)d_out;
    int B = in_sizes[0] / 8;                  // [B,4,2] f32
    int nthreads = (B + 1) / 2;               // 2 boxes per thread
    int threads = 128;
    int blocks = (nthreads + threads - 1) / threads;
    mgiou2dplus_kernel<<<blocks, threads>>>(pred, targ, out, B);
}